// round 14
// baseline (speedup 1.0000x reference)
#include <cuda_runtime.h>
#include <cuda_bf16.h>
#include <cstdint>

#define NCLS    54
#define TILE    128
#define THREADS 128
#define STAGES  4
#define TILE_FLOATS (TILE * NCLS)
#define TILE_BYTES  (TILE_FLOATS * 4)      // 27648
#define CTAS_PER_SM 2

// -log(1 - 53*0.001) = -log(0.947)
#define C0_TERM  0.05445614f
#define LOG2E    1.44269504f

__device__ double g_acc;            // module-load zeroed; reset by last block each run
__device__ unsigned int g_done;

__device__ __forceinline__ uint32_t smem_u32(const void* p) {
    return (uint32_t)__cvta_generic_to_shared(p);
}

__device__ __forceinline__ void mbar_wait(uint32_t mba, int phase) {
    uint32_t done;
    asm volatile("{\n\t.reg .pred p;\n\t"
                 "mbarrier.try_wait.parity.acquire.cta.shared::cta.b64 p, [%1], %2;\n\t"
                 "selp.b32 %0, 1, 0, p;\n\t}"
                 : "=r"(done) : "r"(mba), "r"((uint32_t)phase) : "memory");
    if (!done) {
        asm volatile("{\n\t.reg .pred P1;\n\t"
                     "WL_%=:\n\t"
                     "mbarrier.try_wait.parity.acquire.cta.shared::cta.b64 P1, [%0], %1, 0x989680;\n\t"
                     "@P1 bra.uni WD_%=;\n\t"
                     "bra.uni WL_%=;\n\t"
                     "WD_%=:\n\t}"
                     :: "r"(mba), "r"((uint32_t)phase) : "memory");
    }
}

// issue bulk copy of one tile into buf, completion on bar
__device__ __forceinline__ void issue_tile(const float* __restrict__ logits,
                                           int tile, int batch,
                                           float* buf, uint32_t bar) {
    const int row0  = tile * TILE;
    const int rows  = min(TILE, batch - row0);
    const uint32_t nmain = (uint32_t)(rows * NCLS * 4) & ~15u;
    const char* src = (const char*)(logits + (long long)row0 * NCLS);
    asm volatile("mbarrier.arrive.expect_tx.shared.b64 _, [%0], %1;"
                 :: "r"(bar), "r"(nmain) : "memory");
    asm volatile("cp.async.bulk.shared::cta.global.mbarrier::complete_tx::bytes "
                 "[%0], [%1], %2, [%3];"
                 :: "r"(smem_u32(buf)), "l"(src), "r"(nmain), "r"(bar) : "memory");
}

// softmax row math (hot path: row points into smem -> conflict-free LDS.64)
__device__ __forceinline__ float row_term(const float* __restrict__ row, int t,
                                          const unsigned char* __restrict__ smask) {
    const float2* x2 = (const float2*)row;          // 216B stride, 8B aligned
    float m0 = -3.0e38f, m1 = -3.0e38f, m2 = -3.0e38f, m3 = -3.0e38f;
    #pragma unroll
    for (int k = 0; k < NCLS / 2; k++) {
        float2 v = x2[k];
        if (k & 1) { m2 = fmaxf(m2, v.x); m3 = fmaxf(m3, v.y); }
        else       { m0 = fmaxf(m0, v.x); m1 = fmaxf(m1, v.y); }
    }
    const float m  = fmaxf(fmaxf(m0, m1), fmaxf(m2, m3));
    const float mh = m * LOG2E;

    // reverse order: leaves the SMALLEST matching index (first occurrence, jnp.argmax)
    float s0 = 0.f, s1 = 0.f, s2 = 0.f, s3 = 0.f;
    int am = 0;
    #pragma unroll
    for (int k = NCLS / 2 - 1; k >= 0; k--) {
        float2 v = x2[k];
        float e0 = exp2f(__fmaf_rn(v.x, LOG2E, -mh));
        float e1 = exp2f(__fmaf_rn(v.y, LOG2E, -mh));
        if (k & 1) { s2 += e0; s3 += e1; }
        else       { s0 += e0; s1 += e1; }
        if (v.y == m) am = 2 * k + 1;
        if (v.x == m) am = 2 * k;
    }
    const float sum = (s0 + s1) + (s2 + s3);
    const float xt  = row[t];
    const bool keep = (smask[am] | smask[t]) != 0;
    return keep ? (m + __logf(sum) - xt) : C0_TERM;
}

__global__ void __launch_bounds__(THREADS, CTAS_PER_SM)
importance_loss_ring(const float* __restrict__ logits,
                     const int*   __restrict__ target,
                     const int*   __restrict__ mask,   // bool promoted to int32
                     float* __restrict__ out,
                     int batch)
{
    extern __shared__ __align__(16) float buf[];      // STAGES * TILE_FLOATS
    __shared__ unsigned char smask[64];
    __shared__ float red[THREADS / 32];
    __shared__ __align__(8) unsigned long long mbar[STAGES];

    const int tid    = threadIdx.x;
    const int ntiles = (batch + TILE - 1) / TILE;
    const int stride = gridDim.x;

    if (tid < STAGES)
        asm volatile("mbarrier.init.shared.b64 [%0], 1;"
                     :: "r"(smem_u32(&mbar[tid])) : "memory");
    if (tid < NCLS) smask[tid] = (unsigned char)(mask[tid] != 0);
    __syncthreads();

    // prologue: fill ALL ring slots (slot k <- tile b + k*stride)
    if (tid == 0) {
        #pragma unroll
        for (int k = 0; k < STAGES; k++) {
            int tk = blockIdx.x + k * stride;
            if (tk < ntiles)
                issue_tile(logits, tk, batch, buf + k * TILE_FLOATS, smem_u32(&mbar[k]));
        }
    }

    float acc = 0.0f;
    int i = 0;
    for (int tile = blockIdx.x; tile < ntiles; tile += stride, i++) {
        const int   st    = i & (STAGES - 1);          // slot for tile i (prologue or i-4 refill)
        const int   ph    = (i >> 2) & 1;              // slot st used at iterations st, st+4, ...
        float*      cbuf  = buf + st * TILE_FLOATS;
        const uint32_t cbar = smem_u32(&mbar[st]);

        const int row0 = tile * TILE;
        const int rows = min(TILE, batch - row0);
        int t = 0;
        if (tid < rows) t = target[row0 + tid];       // overlaps with in-flight TMA

        mbar_wait(cbar, ph);

        if (tid < rows) {
            const int full_rows = ((rows * NCLS * 4) & ~15) / (NCLS * 4);
            if (tid < full_rows)                       // hot path: LDS
                acc += row_term(cbuf + tid * NCLS, t, smask);
            else                                       // cold path (2M % 128 == 0: never)
                acc += row_term(logits + (long long)(row0 + tid) * NCLS, t, smask);
        }
        __syncthreads();                               // all lanes done with cbuf

        // refill the just-freed slot with tile i + STAGES (consumed at iteration i+4)
        if (tid == 0) {
            const int nt = tile + STAGES * stride;
            if (nt < ntiles)
                issue_tile(logits, nt, batch, cbuf, cbar);
        }
    }

    // ---- final block reduction (once per CTA) ----
    #pragma unroll
    for (int o = 16; o > 0; o >>= 1)
        acc += __shfl_down_sync(0xffffffffu, acc, o);
    const int lane = tid & 31, w = tid >> 5;
    if (lane == 0) red[w] = acc;
    __syncthreads();

    if (tid == 0) {
        float bs = 0.0f;
        #pragma unroll
        for (int j = 0; j < THREADS / 32; j++) bs += red[j];
        atomicAdd(&g_acc, (double)bs);
        __threadfence();
        unsigned int done = atomicAdd(&g_done, 1u);
        if (done == gridDim.x - 1) {
            double total = atomicAdd(&g_acc, 0.0);     // atomic read via L2
            out[0] = (float)(total / (double)batch);
            g_acc  = 0.0;                              // reset for next graph replay
            g_done = 0u;
        }
    }
}

extern "C" void kernel_launch(void* const* d_in, const int* in_sizes, int n_in,
                              void* d_out, int out_size)
{
    const float* logits = (const float*)d_in[0];
    const int*   target = (const int*)d_in[1];
    const int*   mask   = (const int*)d_in[2];
    float* out = (float*)d_out;

    const int batch = in_sizes[1];

    static int grid = 0;
    if (grid == 0) {
        int dev = 0, sms = 152;
        cudaGetDevice(&dev);
        cudaDeviceGetAttribute(&sms, cudaDevAttrMultiProcessorCount, dev);
        cudaFuncSetAttribute(importance_loss_ring,
                             cudaFuncAttributeMaxDynamicSharedMemorySize,
                             STAGES * TILE_BYTES);
        grid = sms * CTAS_PER_SM;
    }

    importance_loss_ring<<<grid, THREADS, STAGES * TILE_BYTES>>>(logits, target, mask, out, batch);
}

// round 15
// speedup vs baseline: 1.0837x; 1.0837x over previous
#include <cuda_runtime.h>
#include <cuda_bf16.h>
#include <cstdint>

#define NCLS    54
#define TILE    128
#define THREADS 128
#define TILE_FLOATS (TILE * NCLS)
#define TILE_BYTES  (TILE_FLOATS * 4)      // 27648
#define CTAS_PER_SM 4

// -log(1 - 53*0.001) = -log(0.947)
#define C0_TERM  0.05445614f
#define LOG2E    1.44269504f

__device__ double g_acc;            // module-load zeroed; reset by last block each run
__device__ unsigned int g_done;

__device__ __forceinline__ uint32_t smem_u32(const void* p) {
    return (uint32_t)__cvta_generic_to_shared(p);
}

__device__ __forceinline__ void mbar_wait(uint32_t mba, int phase) {
    uint32_t done;
    asm volatile("{\n\t.reg .pred p;\n\t"
                 "mbarrier.try_wait.parity.acquire.cta.shared::cta.b64 p, [%1], %2;\n\t"
                 "selp.b32 %0, 1, 0, p;\n\t}"
                 : "=r"(done) : "r"(mba), "r"((uint32_t)phase) : "memory");
    if (!done) {
        asm volatile("{\n\t.reg .pred P1;\n\t"
                     "WL_%=:\n\t"
                     "mbarrier.try_wait.parity.acquire.cta.shared::cta.b64 P1, [%0], %1, 0x989680;\n\t"
                     "@P1 bra.uni WD_%=;\n\t"
                     "bra.uni WL_%=;\n\t"
                     "WD_%=:\n\t}"
                     :: "r"(mba), "r"((uint32_t)phase) : "memory");
    }
}

// issue bulk copy of one tile into buf, completion on bar
__device__ __forceinline__ void issue_tile(const float* __restrict__ logits,
                                           int tile, int batch,
                                           float* buf, uint32_t bar) {
    const int row0  = tile * TILE;
    const int rows  = min(TILE, batch - row0);
    const uint32_t nmain = (uint32_t)(rows * NCLS * 4) & ~15u;
    const char* src = (const char*)(logits + (long long)row0 * NCLS);
    asm volatile("mbarrier.arrive.expect_tx.shared.b64 _, [%0], %1;"
                 :: "r"(bar), "r"(nmain) : "memory");
    asm volatile("cp.async.bulk.shared::cta.global.mbarrier::complete_tx::bytes "
                 "[%0], [%1], %2, [%3];"
                 :: "r"(smem_u32(buf)), "l"(src), "r"(nmain), "r"(bar) : "memory");
}

// row term: single LDS pass into registers, then all math from registers.
// xt is passed in (single dynamic-index LDS done by the caller).
__device__ __forceinline__ float row_term_reg(const float2* __restrict__ x2,
                                              float xt, int t,
                                              const unsigned char* __restrict__ smask) {
    float r[NCLS];
    // one pass of 27 LDS.64, issued back-to-back (ptxas will batch them)
    #pragma unroll
    for (int k = 0; k < NCLS / 2; k++) {
        float2 v = x2[k];
        r[2 * k]     = v.x;
        r[2 * k + 1] = v.y;
    }

    // max via 4 independent chains (registers only)
    float m0 = -3.0e38f, m1 = -3.0e38f, m2 = -3.0e38f, m3 = -3.0e38f;
    #pragma unroll
    for (int j = 0; j < NCLS; j += 4) {
        m0 = fmaxf(m0, r[j]);
        m1 = fmaxf(m1, r[j + 1]);
        m2 = fmaxf(m2, r[j + 2]);
        m3 = fmaxf(m3, r[j + 3]);
    }
    m0 = fmaxf(m0, r[52]); m1 = fmaxf(m1, r[53]);
    const float m  = fmaxf(fmaxf(m0, m1), fmaxf(m2, m3));
    const float mh = m * LOG2E;

    // exp-sum + argmax (reverse => smallest matching index, jnp.argmax semantics)
    float s0 = 0.f, s1 = 0.f, s2 = 0.f, s3 = 0.f;
    int am = 0;
    #pragma unroll
    for (int j = NCLS - 2; j >= 0; j -= 2) {
        float e0 = exp2f(__fmaf_rn(r[j],     LOG2E, -mh));
        float e1 = exp2f(__fmaf_rn(r[j + 1], LOG2E, -mh));
        if (j & 2) { s2 += e0; s3 += e1; }
        else       { s0 += e0; s1 += e1; }
        if (r[j + 1] == m) am = j + 1;
        if (r[j]     == m) am = j;
    }
    const float sum = (s0 + s1) + (s2 + s3);
    const bool keep = (smask[am] | smask[t]) != 0;
    return keep ? (m + __logf(sum) - xt) : C0_TERM;
}

__global__ void __launch_bounds__(THREADS, CTAS_PER_SM)
importance_loss_persist(const float* __restrict__ logits,
                        const int*   __restrict__ target,
                        const int*   __restrict__ mask,   // bool promoted to int32
                        float* __restrict__ out,
                        int batch)
{
    extern __shared__ __align__(16) float buf[];          // 2 * TILE_FLOATS
    __shared__ unsigned char smask[64];
    __shared__ float red[THREADS / 32];
    __shared__ __align__(8) unsigned long long mbar[2];

    const int tid    = threadIdx.x;
    const int ntiles = (batch + TILE - 1) / TILE;
    const int stride = gridDim.x;

    if (tid < 2)
        asm volatile("mbarrier.init.shared.b64 [%0], 1;"
                     :: "r"(smem_u32(&mbar[tid])) : "memory");
    if (tid < NCLS) smask[tid] = (unsigned char)(mask[tid] != 0);
    __syncthreads();

    const uint32_t bar0 = smem_u32(&mbar[0]);
    const uint32_t bar1 = smem_u32(&mbar[1]);

    int tile = blockIdx.x;
    if (tid == 0 && tile < ntiles)
        issue_tile(logits, tile, batch, buf, bar0);

    float acc = 0.0f;
    int parity = 0, phA = 0, phB = 0;

    for (; tile < ntiles; tile += stride) {
        const int nextt = tile + stride;
        float*   cbuf = parity ? (buf + TILE_FLOATS) : buf;
        float*   obuf = parity ? buf : (buf + TILE_FLOATS);
        const uint32_t cbar = parity ? bar1 : bar0;
        const uint32_t obar = parity ? bar0 : bar1;

        // keep the DRAM stream busy: queue next tile before consuming current
        if (tid == 0 && nextt < ntiles)
            issue_tile(logits, nextt, batch, obuf, obar);

        const int row0 = tile * TILE;
        const int rows = min(TILE, batch - row0);
        int t = 0;
        if (tid < rows) t = target[row0 + tid];           // overlaps with TMA

        const int ph = parity ? phB : phA;
        mbar_wait(cbar, ph);
        if (parity) phB ^= 1; else phA ^= 1;

        if (tid < rows) {
            const int full_rows = ((rows * NCLS * 4) & ~15) / (NCLS * 4);
            if (tid < full_rows) {                        // hot path: regs from LDS
                const float xt = cbuf[tid * NCLS + t];
                acc += row_term_reg((const float2*)(cbuf + tid * NCLS), xt, t, smask);
            } else {                                      // cold path (2M % 128 == 0: never)
                const float* g = logits + (long long)(row0 + tid) * NCLS;
                acc += row_term_reg((const float2*)g, g[t], t, smask);
            }
        }
        __syncthreads();                                  // release cbuf for re-fill
        parity ^= 1;
    }

    // ---- final block reduction (once per CTA) ----
    #pragma unroll
    for (int o = 16; o > 0; o >>= 1)
        acc += __shfl_down_sync(0xffffffffu, acc, o);
    const int lane = tid & 31, w = tid >> 5;
    if (lane == 0) red[w] = acc;
    __syncthreads();

    if (tid == 0) {
        float bs = 0.0f;
        #pragma unroll
        for (int j = 0; j < THREADS / 32; j++) bs += red[j];
        atomicAdd(&g_acc, (double)bs);
        __threadfence();
        unsigned int done = atomicAdd(&g_done, 1u);
        if (done == gridDim.x - 1) {
            double total = atomicAdd(&g_acc, 0.0);        // atomic read via L2
            out[0] = (float)(total / (double)batch);
            g_acc  = 0.0;                                 // reset for next graph replay
            g_done = 0u;
        }
    }
}

extern "C" void kernel_launch(void* const* d_in, const int* in_sizes, int n_in,
                              void* d_out, int out_size)
{
    const float* logits = (const float*)d_in[0];
    const int*   target = (const int*)d_in[1];
    const int*   mask   = (const int*)d_in[2];
    float* out = (float*)d_out;

    const int batch = in_sizes[1];

    static int grid = 0;
    if (grid == 0) {
        int dev = 0, sms = 148;
        cudaGetDevice(&dev);
        cudaDeviceGetAttribute(&sms, cudaDevAttrMultiProcessorCount, dev);
        cudaFuncSetAttribute(importance_loss_persist,
                             cudaFuncAttributeMaxDynamicSharedMemorySize,
                             2 * TILE_BYTES);
        grid = sms * CTAS_PER_SM;
    }

    importance_loss_persist<<<grid, THREADS, 2 * TILE_BYTES>>>(logits, target, mask, out, batch);
}

// round 16
// speedup vs baseline: 1.0871x; 1.0032x over previous
#include <cuda_runtime.h>
#include <cuda_bf16.h>
#include <cstdint>

#define NCLS    54
#define TILE    64
#define THREADS 64
#define TILE_FLOATS (TILE * NCLS)
#define TILE_BYTES  (TILE_FLOATS * 4)      // 13824
#define CTAS_PER_SM 8

// -log(1 - 53*0.001) = -log(0.947)
#define C0_TERM  0.05445614f
#define LOG2E    1.44269504f

__device__ double g_acc;            // module-load zeroed; reset by last block each run
__device__ unsigned int g_done;

__device__ __forceinline__ uint32_t smem_u32(const void* p) {
    return (uint32_t)__cvta_generic_to_shared(p);
}

__device__ __forceinline__ void mbar_wait(uint32_t mba, int phase) {
    uint32_t done;
    asm volatile("{\n\t.reg .pred p;\n\t"
                 "mbarrier.try_wait.parity.acquire.cta.shared::cta.b64 p, [%1], %2;\n\t"
                 "selp.b32 %0, 1, 0, p;\n\t}"
                 : "=r"(done) : "r"(mba), "r"((uint32_t)phase) : "memory");
    if (!done) {
        asm volatile("{\n\t.reg .pred P1;\n\t"
                     "WL_%=:\n\t"
                     "mbarrier.try_wait.parity.acquire.cta.shared::cta.b64 P1, [%0], %1, 0x989680;\n\t"
                     "@P1 bra.uni WD_%=;\n\t"
                     "bra.uni WL_%=;\n\t"
                     "WD_%=:\n\t}"
                     :: "r"(mba), "r"((uint32_t)phase) : "memory");
    }
}

// issue bulk copy of one tile into buf, completion on bar
__device__ __forceinline__ void issue_tile(const float* __restrict__ logits,
                                           int tile, int batch,
                                           float* buf, uint32_t bar) {
    const int row0  = tile * TILE;
    const int rows  = min(TILE, batch - row0);
    const uint32_t nmain = (uint32_t)(rows * NCLS * 4) & ~15u;
    const char* src = (const char*)(logits + (long long)row0 * NCLS);
    asm volatile("mbarrier.arrive.expect_tx.shared.b64 _, [%0], %1;"
                 :: "r"(bar), "r"(nmain) : "memory");
    asm volatile("cp.async.bulk.shared::cta.global.mbarrier::complete_tx::bytes "
                 "[%0], [%1], %2, [%3];"
                 :: "r"(smem_u32(buf)), "l"(src), "r"(nmain), "r"(bar) : "memory");
}

// softmax row math (hot path: row points into smem -> conflict-free LDS.64)
__device__ __forceinline__ float row_term(const float* __restrict__ row, int t,
                                          const unsigned char* __restrict__ smask) {
    const float2* x2 = (const float2*)row;          // 216B stride, 8B aligned
    float m0 = -3.0e38f, m1 = -3.0e38f, m2 = -3.0e38f, m3 = -3.0e38f;
    #pragma unroll
    for (int k = 0; k < NCLS / 2; k++) {
        float2 v = x2[k];
        if (k & 1) { m2 = fmaxf(m2, v.x); m3 = fmaxf(m3, v.y); }
        else       { m0 = fmaxf(m0, v.x); m1 = fmaxf(m1, v.y); }
    }
    const float m  = fmaxf(fmaxf(m0, m1), fmaxf(m2, m3));
    const float mh = m * LOG2E;

    // reverse order: leaves the SMALLEST matching index (first occurrence, jnp.argmax)
    float s0 = 0.f, s1 = 0.f, s2 = 0.f, s3 = 0.f;
    int am = 0;
    #pragma unroll
    for (int k = NCLS / 2 - 1; k >= 0; k--) {
        float2 v = x2[k];
        float e0 = exp2f(__fmaf_rn(v.x, LOG2E, -mh));
        float e1 = exp2f(__fmaf_rn(v.y, LOG2E, -mh));
        if (k & 1) { s2 += e0; s3 += e1; }
        else       { s0 += e0; s1 += e1; }
        if (v.y == m) am = 2 * k + 1;
        if (v.x == m) am = 2 * k;
    }
    const float sum = (s0 + s1) + (s2 + s3);
    const float xt  = row[t];
    const bool keep = (smask[am] | smask[t]) != 0;
    return keep ? (m + __logf(sum) - xt) : C0_TERM;
}

__global__ void __launch_bounds__(THREADS, CTAS_PER_SM)
importance_loss_persist8(const float* __restrict__ logits,
                         const int*   __restrict__ target,
                         const int*   __restrict__ mask,   // bool promoted to int32
                         float* __restrict__ out,
                         int batch)
{
    extern __shared__ __align__(16) float buf[];          // 2 * TILE_FLOATS
    __shared__ unsigned char smask[64];
    __shared__ float red[THREADS / 32];
    __shared__ __align__(8) unsigned long long mbar[2];

    const int tid    = threadIdx.x;
    const int ntiles = (batch + TILE - 1) / TILE;
    const int stride = gridDim.x;

    if (tid < 2)
        asm volatile("mbarrier.init.shared.b64 [%0], 1;"
                     :: "r"(smem_u32(&mbar[tid])) : "memory");
    if (tid < NCLS) smask[tid] = (unsigned char)(mask[tid] != 0);
    __syncthreads();

    const uint32_t bar0 = smem_u32(&mbar[0]);
    const uint32_t bar1 = smem_u32(&mbar[1]);

    int tile = blockIdx.x;
    if (tid == 0 && tile < ntiles)
        issue_tile(logits, tile, batch, buf, bar0);

    float acc = 0.0f;
    int parity = 0, phA = 0, phB = 0;

    for (; tile < ntiles; tile += stride) {
        const int nextt = tile + stride;
        float*   cbuf = parity ? (buf + TILE_FLOATS) : buf;
        float*   obuf = parity ? buf : (buf + TILE_FLOATS);
        const uint32_t cbar = parity ? bar1 : bar0;
        const uint32_t obar = parity ? bar0 : bar1;

        // keep the DRAM stream busy: queue next tile before consuming current
        if (tid == 0 && nextt < ntiles)
            issue_tile(logits, nextt, batch, obuf, obar);

        const int row0 = tile * TILE;
        const int rows = min(TILE, batch - row0);
        int t = 0;
        if (tid < rows) t = target[row0 + tid];           // overlaps with TMA

        const int ph = parity ? phB : phA;
        mbar_wait(cbar, ph);
        if (parity) phB ^= 1; else phA ^= 1;

        if (tid < rows) {
            const int full_rows = ((rows * NCLS * 4) & ~15) / (NCLS * 4);
            if (tid < full_rows)                           // hot path: LDS
                acc += row_term(cbuf + tid * NCLS, t, smask);
            else                                           // cold path (2M % 64 == 0: never)
                acc += row_term(logits + (long long)(row0 + tid) * NCLS, t, smask);
        }
        __syncthreads();                                   // release cbuf for re-fill
        parity ^= 1;
    }

    // ---- final block reduction (once per CTA) ----
    #pragma unroll
    for (int o = 16; o > 0; o >>= 1)
        acc += __shfl_down_sync(0xffffffffu, acc, o);
    const int lane = tid & 31, w = tid >> 5;
    if (lane == 0) red[w] = acc;
    __syncthreads();

    if (tid == 0) {
        float bs = 0.0f;
        #pragma unroll
        for (int j = 0; j < THREADS / 32; j++) bs += red[j];
        atomicAdd(&g_acc, (double)bs);
        __threadfence();
        unsigned int done = atomicAdd(&g_done, 1u);
        if (done == gridDim.x - 1) {
            double total = atomicAdd(&g_acc, 0.0);         // atomic read via L2
            out[0] = (float)(total / (double)batch);
            g_acc  = 0.0;                                  // reset for next graph replay
            g_done = 0u;
        }
    }
}

extern "C" void kernel_launch(void* const* d_in, const int* in_sizes, int n_in,
                              void* d_out, int out_size)
{
    const float* logits = (const float*)d_in[0];
    const int*   target = (const int*)d_in[1];
    const int*   mask   = (const int*)d_in[2];
    float* out = (float*)d_out;

    const int batch = in_sizes[1];

    static int grid = 0;
    if (grid == 0) {
        int dev = 0, sms = 148;
        cudaGetDevice(&dev);
        cudaDeviceGetAttribute(&sms, cudaDevAttrMultiProcessorCount, dev);
        cudaFuncSetAttribute(importance_loss_persist8,
                             cudaFuncAttributeMaxDynamicSharedMemorySize,
                             2 * TILE_BYTES);
        grid = sms * CTAS_PER_SM;
    }

    importance_loss_persist8<<<grid, THREADS, 2 * TILE_BYTES>>>(logits, target, mask, out, batch);
}